// round 12
// baseline (speedup 1.0000x reference)
#include <cuda_runtime.h>
#include <cuda_bf16.h>
#include <cstdint>
#include <math.h>

#define EPS 1e-6f
#define B_  8
#define LQ  1024
#define LK  8192
#define D_  256
#define DC  128

// ---------------- scratch (device globals; no allocations allowed) ----------
__device__ __nv_bfloat16 g_qp[B_ * LQ * DC];   // q' = q @ W_up  (bf16)      2 MB
__device__ float         g_qsq[B_ * LQ];       // ||q||^2 (fp32)
__device__ __nv_bfloat16 g_kc[B_ * LK * DC];   // dequantized k_c (bf16)    16 MB
__device__ float         g_ksq[B_ * LK];       // ||k||^2 via Gram form
__device__ __nv_bfloat16 g_G[DC * DC];         // G = W^T W (bf16)

__device__ __forceinline__ uint32_t smem_u32(const void* p) {
    return (uint32_t)__cvta_generic_to_shared(p);
}
#define CP_ASYNC16(dst, src) \
    asm volatile("cp.async.cg.shared.global [%0], [%1], 16;" :: "r"(dst), "l"(src))
#define CP_COMMIT() asm volatile("cp.async.commit_group;" ::: "memory")
#define CP_WAIT(n)  asm volatile("cp.async.wait_group %0;" :: "n"(n) : "memory")

// smem tile: 128 rows x 256B data + 16B pad -> stride 272B (17 uint4)
#define TSTRIDE 272
#define TILE_BYTES (128 * TSTRIDE)   // 34816

// async-copy one 128x128 bf16 tile (global row-major, 256B rows) into smem
__device__ __forceinline__ void load_tile_async(uint32_t base,
                                                const __nv_bfloat16* g, int t) {
#pragma unroll
    for (int it = 0; it < 8; ++it) {
        int idx = t + it * 256;          // 16B chunk id 0..2047
        int r = idx >> 4, cc = idx & 15;
        CP_ASYNC16(base + r * TSTRIDE + cc * 16,
                   (const char*)g + r * 256 + cc * 16);
    }
}

// ---------------- kernel 1: fused prep = (q' & q_sq) + Gram G ---------------
__global__ __launch_bounds__(256) void prep_kernel(const float* __restrict__ q,
                                                   const float* __restrict__ W) {
    int t = threadIdx.x;
    if (blockIdx.x >= 1024) {
        int id = (blockIdx.x - 1024) * 256 + t;  // 0..16383
        int c1 = id >> 7, c2 = id & 127;
        float acc = 0.f;
#pragma unroll 8
        for (int d = 0; d < D_; ++d)
            acc = fmaf(__ldg(W + d * DC + c1), __ldg(W + d * DC + c2), acc);
        g_G[c1 * DC + c2] = __float2bfloat16(acc);
        return;
    }
    __shared__ float qs[8 * 256];
    size_t base = (size_t)blockIdx.x * 2048;
#pragma unroll
    for (int i = t; i < 2048; i += 256) qs[i] = q[base + i];
    __syncthreads();

    int lane = t & 31, w = t >> 5;
    float s = 0.f;
#pragma unroll
    for (int i = 0; i < 8; ++i) {
        float v = qs[w * 256 + lane + i * 32];
        s = fmaf(v, v, s);
    }
#pragma unroll
    for (int o = 16; o; o >>= 1) s += __shfl_xor_sync(0xffffffffu, s, o);
    if (lane == 0) g_qsq[blockIdx.x * 8 + w] = s;

    const float4* W4 = (const float4*)W;
    float ax = 0.f, ay = 0.f, az = 0.f, aw = 0.f;
#pragma unroll 4
    for (int d = 0; d < D_; ++d) {
        float qv = qs[w * 256 + d];
        float4 ww = W4[d * 32 + lane];
        ax = fmaf(qv, ww.x, ax);
        ay = fmaf(qv, ww.y, ay);
        az = fmaf(qv, ww.z, az);
        aw = fmaf(qv, ww.w, aw);
    }
    __nv_bfloat162 p01 = __floats2bfloat162_rn(ax, ay);
    __nv_bfloat162 p23 = __floats2bfloat162_rn(az, aw);
    uint2 wv = make_uint2(*reinterpret_cast<unsigned int*>(&p01),
                          *reinterpret_cast<unsigned int*>(&p23));
    ((uint2*)g_qp)[(blockIdx.x * 8 + w) * 32 + lane] = wv;
}

// ---------------- kernel 2: int4-code dequant -> bf16 -----------------------
__global__ void deq_kernel(const int* __restrict__ kq,
                           const float* __restrict__ sc,
                           const float* __restrict__ zp) {
    int i = blockIdx.x * 256 + threadIdx.x;
    int4 v = ((const int4*)kq)[i];
    int flat = i << 2;
    int c = flat & (DC - 1);
    int b = flat >> 20;
    float4 s = *(const float4*)(sc + b * DC + c);
    float4 z = *(const float4*)(zp + b * DC + c);
    float f0 = s.x * ((float)v.x - z.x);
    float f1 = s.y * ((float)v.y - z.y);
    float f2 = s.z * ((float)v.z - z.z);
    float f3 = s.w * ((float)v.w - z.w);
    __nv_bfloat162 p01 = __floats2bfloat162_rn(f0, f1);
    __nv_bfloat162 p23 = __floats2bfloat162_rn(f2, f3);
    uint2 wv = make_uint2(*reinterpret_cast<unsigned int*>(&p01),
                          *reinterpret_cast<unsigned int*>(&p23));
    ((uint2*)g_kc)[i] = wv;
}

// ---------------- mma.sync 128x128x128 block --------------------------------
__device__ __forceinline__ void block_mma_128(uint32_t smA, uint32_t smB,
                                              int lane, int warp_m, int warp_n,
                                              float acc[2][8][4]) {
#pragma unroll
    for (int kk = 0; kk < 8; ++kk) {
        uint32_t a[2][4];
#pragma unroll
        for (int mi = 0; mi < 2; ++mi) {
            int row = warp_m * 32 + mi * 16 + (lane & 15);
            uint32_t addr = smA + row * TSTRIDE + kk * 32 + ((lane >> 4) << 4);
            asm volatile("ldmatrix.sync.aligned.m8n8.x4.shared.b16 {%0,%1,%2,%3}, [%4];"
                         : "=r"(a[mi][0]), "=r"(a[mi][1]), "=r"(a[mi][2]), "=r"(a[mi][3])
                         : "r"(addr));
        }
        uint32_t bb[8][2];
#pragma unroll
        for (int nn = 0; nn < 4; ++nn) {
            int nrow = warp_n * 64 + nn * 16 + (lane & 7) + (((lane >> 4) & 1) << 3);
            uint32_t addr = smB + nrow * TSTRIDE + kk * 32 + (((lane >> 3) & 1) << 4);
            uint32_t r0, r1, r2, r3;
            asm volatile("ldmatrix.sync.aligned.m8n8.x4.shared.b16 {%0,%1,%2,%3}, [%4];"
                         : "=r"(r0), "=r"(r1), "=r"(r2), "=r"(r3)
                         : "r"(addr));
            bb[2 * nn][0] = r0; bb[2 * nn][1] = r1;
            bb[2 * nn + 1][0] = r2; bb[2 * nn + 1][1] = r3;
        }
#pragma unroll
        for (int mi = 0; mi < 2; ++mi)
#pragma unroll
            for (int ni = 0; ni < 8; ++ni)
                asm volatile(
                    "mma.sync.aligned.m16n8k16.row.col.f32.bf16.bf16.f32 "
                    "{%0,%1,%2,%3}, {%4,%5,%6,%7}, {%8,%9}, {%0,%1,%2,%3};"
                    : "+f"(acc[mi][ni][0]), "+f"(acc[mi][ni][1]),
                      "+f"(acc[mi][ni][2]), "+f"(acc[mi][ni][3])
                    : "r"(a[mi][0]), "r"(a[mi][1]), "r"(a[mi][2]), "r"(a[mi][3]),
                      "r"(bb[ni][0]), "r"(bb[ni][1]));
    }
}

// ---------------- kernel 3: k_sq via Gram quadratic form --------------------
__global__ __launch_bounds__(256) void ksq_kernel() {
    extern __shared__ char smem[];
    __nv_bfloat16* smA = (__nv_bfloat16*)smem;
    float* s_acc = (float*)(smem + 2 * TILE_BYTES);
    int t = threadIdx.x;
    int k0 = blockIdx.x * 128;

    const uint4* gA = (const uint4*)(g_kc + (size_t)k0 * DC);
    const uint4* gB = (const uint4*)g_G;
    uint4* sA4 = (uint4*)smem;
    uint4* sB4 = (uint4*)(smem + TILE_BYTES);
#pragma unroll
    for (int i = t; i < 2048; i += 256) {
        int r = i >> 4, ch = i & 15;
        sA4[r * 17 + ch] = gA[i];
        sB4[r * 17 + ch] = gB[i];
    }
    if (t < 128) s_acc[t] = 0.f;
    __syncthreads();

    int lane = t & 31, wid = t >> 5;
    int warp_m = wid & 3, warp_n = wid >> 2;
    float acc[2][8][4];
#pragma unroll
    for (int mi = 0; mi < 2; ++mi)
#pragma unroll
        for (int ni = 0; ni < 8; ++ni)
#pragma unroll
            for (int e = 0; e < 4; ++e) acc[mi][ni][e] = 0.f;

    block_mma_128(smem_u32(smem), smem_u32(smem + TILE_BYTES),
                  lane, warp_m, warp_n, acc);

    int g = lane >> 2, tg = lane & 3;
#pragma unroll
    for (int mi = 0; mi < 2; ++mi)
#pragma unroll
        for (int h = 0; h < 2; ++h) {
            int row = warp_m * 32 + mi * 16 + h * 8 + g;
            float p = 0.f;
#pragma unroll
            for (int ni = 0; ni < 8; ++ni) {
                int col = warp_n * 64 + ni * 8 + 2 * tg;
                float kc0 = __bfloat162float(smA[row * 136 + col]);
                float kc1 = __bfloat162float(smA[row * 136 + col + 1]);
                p = fmaf(acc[mi][ni][2 * h + 0], kc0, p);
                p = fmaf(acc[mi][ni][2 * h + 1], kc1, p);
            }
            atomicAdd(&s_acc[row], p);
        }
    __syncthreads();
    if (t < 128) g_ksq[k0 + t] = s_acc[t];
}

// ---------------- kernel 4: distance kernel (2 k-tiles/CTA, occ-pinned) ----
// SMEM: A[0,34816) B0[34816,69632) B1[69632,104448)
//       s_ks[104448,105472)  s_qsq[105472,105984)
#define DIST_SMEM 105984

__global__ __launch_bounds__(256, 2)
void dist_kernel(float* __restrict__ out) {
    extern __shared__ char smem[];
    float* s_ks  = (float*)(smem + 104448);   // 256 floats
    float* s_qsq = (float*)(smem + 105472);   // 128 floats
    const int t = threadIdx.x;
    const int lane = t & 31, wid = t >> 5;
    const int warp_m = wid & 3, warp_n = wid >> 2;
    const int b = blockIdx.z, qt = blockIdx.y, kh = blockIdx.x;
    const int q0 = qt * 128, k0 = kh * 256;

    uint32_t smA  = smem_u32(smem);
    uint32_t smB0 = smA + TILE_BYTES;
    uint32_t smB1 = smB0 + TILE_BYTES;

    const __nv_bfloat16* kc = g_kc + (size_t)(b * LK + k0) * DC;

    // group0 = {A, B0}; group1 = {B1}
    load_tile_async(smA, g_qp + (size_t)(b * LQ + q0) * DC, t);
    load_tile_async(smB0, kc, t);
    CP_COMMIT();
    load_tile_async(smB1, kc + 128 * DC, t);
    CP_COMMIT();

    // norm tables (plain stores; covered by barrier below)
    if (t < 256) s_ks[t] = __ldg(g_ksq + b * LK + k0 + t);
    if (t < 128) s_qsq[t] = g_qsq[b * LQ + q0 + t];

    CP_WAIT(1);
    __syncthreads();   // A, B0, tables visible

    // ------------- row constants -------------
    const int g = lane >> 2, tg = lane & 3;
    const float OME = 1.0f - EPS;
    const float E1 = 1.0f - OME;
    const float CDEN = fmaf(E1, E1, EPS);
    const float L2CDEN = __log2f(CDEN);
    const float THRC = 5.0e3f * CDEN;
    const float LN2 = 0.69314718056f, TWO_LN2 = 1.38629436112f;

    float qs_r[4], eq_r[4];
#pragma unroll
    for (int mi = 0; mi < 2; ++mi)
#pragma unroll
        for (int h = 0; h < 2; ++h) {
            int row = warp_m * 32 + mi * 16 + h * 8 + g;
            float qs = s_qsq[row];
            qs_r[mi * 2 + h] = qs;
            eq_r[mi * 2 + h] = 1.0f - fminf(qs, OME);
        }
    const bool rows_c = (qs_r[0] >= OME) & (qs_r[1] >= OME) &
                        (qs_r[2] >= OME) & (qs_r[3] >= OME);
    float* obase = out + (size_t)(b * LQ + q0) * LK + k0;

#pragma unroll
    for (int tt = 0; tt < 2; ++tt) {
        if (tt == 1) {
            CP_WAIT(0);
            __syncthreads();   // B1 visible
        }
        float acc[2][8][4];
#pragma unroll
        for (int mi = 0; mi < 2; ++mi)
#pragma unroll
            for (int ni = 0; ni < 8; ++ni)
#pragma unroll
                for (int e = 0; e < 4; ++e) acc[mi][ni][e] = 0.f;

        block_mma_128(smA, tt ? smB1 : smB0, lane, warp_m, warp_n, acc);

        // ------------- epilogue tile tt (overlaps B1 arrival when tt==0) ----
        const float* ksp = s_ks + tt * 128;
        float* otile = obase + tt * 128;
#pragma unroll
        for (int ni = 0; ni < 8; ++ni) {
            int col = warp_n * 64 + ni * 8 + 2 * tg;
            float ks0 = ksp[col], ks1 = ksp[col + 1];
            if (rows_c & (ks0 >= OME) & (ks1 >= OME)) {
                // den == CDEN for all outputs of this pair: 1 MUFU / element
#pragma unroll
                for (int mi = 0; mi < 2; ++mi)
#pragma unroll
                    for (int h = 0; h < 2; ++h) {
                        float qs = qs_r[mi * 2 + h];
                        float d0 = fmaxf(fmaf(-2.0f, acc[mi][ni][2 * h + 0], qs + ks0), 0.0f);
                        float d1 = fmaxf(fmaf(-2.0f, acc[mi][ni][2 * h + 1], qs + ks1), 0.0f);
                        float r0 = (d0 > THRC)
                            ? fmaf(LN2, __log2f(d0) - L2CDEN, TWO_LN2)
                            : acoshf(1.0f + 2.0f * d0 / CDEN);
                        float r1 = (d1 > THRC)
                            ? fmaf(LN2, __log2f(d1) - L2CDEN, TWO_LN2)
                            : acoshf(1.0f + 2.0f * d1 / CDEN);
                        int row = warp_m * 32 + mi * 16 + h * 8 + g;
                        *(float2*)(otile + (size_t)row * LK + col) = make_float2(r0, r1);
                    }
            } else {
                float ek0 = 1.0f - fminf(ks0, OME);
                float ek1 = 1.0f - fminf(ks1, OME);
#pragma unroll
                for (int mi = 0; mi < 2; ++mi)
#pragma unroll
                    for (int h = 0; h < 2; ++h) {
                        float qs = qs_r[mi * 2 + h], eq = eq_r[mi * 2 + h];
                        float d0 = fmaxf(fmaf(-2.0f, acc[mi][ni][2 * h + 0], qs + ks0), 0.0f);
                        float d1 = fmaxf(fmaf(-2.0f, acc[mi][ni][2 * h + 1], qs + ks1), 0.0f);
                        float den0 = fmaf(eq, ek0, EPS);
                        float den1 = fmaf(eq, ek1, EPS);
                        float r0 = (d0 > 5.0e3f * den0)
                            ? fmaf(LN2, __log2f(d0) - __log2f(den0), TWO_LN2)
                            : acoshf(1.0f + 2.0f * d0 / den0);
                        float r1 = (d1 > 5.0e3f * den1)
                            ? fmaf(LN2, __log2f(d1) - __log2f(den1), TWO_LN2)
                            : acoshf(1.0f + 2.0f * d1 / den1);
                        int row = warp_m * 32 + mi * 16 + h * 8 + g;
                        *(float2*)(otile + (size_t)row * LK + col) = make_float2(r0, r1);
                    }
            }
        }
    }
}

// ---------------- launch ----------------------------------------------------
extern "C" void kernel_launch(void* const* d_in, const int* in_sizes, int n_in,
                              void* d_out, int out_size) {
    (void)in_sizes; (void)n_in; (void)out_size;
    const float* q   = (const float*)d_in[0];
    const int*   kq  = (const int*)d_in[1];
    const float* ksc = (const float*)d_in[2];
    const float* kzp = (const float*)d_in[3];
    const float* W   = (const float*)d_in[4];
    float* out = (float*)d_out;

    const int KSQ_SMEM = 2 * TILE_BYTES + 512;  // 70144
    cudaFuncSetAttribute(ksq_kernel, cudaFuncAttributeMaxDynamicSharedMemorySize, KSQ_SMEM);
    cudaFuncSetAttribute(dist_kernel, cudaFuncAttributeMaxDynamicSharedMemorySize, DIST_SMEM);

    prep_kernel<<<1088, 256>>>(q, W);                                 // launch 0
    deq_kernel<<<(B_ * LK * DC) / 4 / 256, 256>>>(kq, ksc, kzp);      // launch 1
    ksq_kernel<<<(B_ * LK) / 128, 256, KSQ_SMEM>>>();                 // launch 2
    dist_kernel<<<dim3(LK / 256, LQ / 128, B_), 256, DIST_SMEM>>>(out);  // launch 3
}

// round 13
// speedup vs baseline: 1.6111x; 1.6111x over previous
#include <cuda_runtime.h>
#include <cuda_bf16.h>
#include <cstdint>
#include <math.h>

#define EPS 1e-6f
#define B_  8
#define LQ  1024
#define LK  8192
#define D_  256
#define DC  128

// ---------------- scratch (device globals; no allocations allowed) ----------
__device__ __nv_bfloat16 g_qp[B_ * LQ * DC];   // q' = q @ W_up  (bf16)      2 MB
__device__ float         g_qsq[B_ * LQ];       // ||q||^2 (fp32)
__device__ __nv_bfloat16 g_kc[B_ * LK * DC];   // dequantized k_c (bf16)    16 MB
__device__ float         g_ksq[B_ * LK];       // ||k||^2 via Gram form
__device__ __nv_bfloat16 g_G[DC * DC];         // G = W^T W (bf16)

__device__ __forceinline__ uint32_t smem_u32(const void* p) {
    return (uint32_t)__cvta_generic_to_shared(p);
}

// smem tile: rows x 256B data + 16B pad -> stride 272B (17 uint4)
#define TSTRIDE 272
#define TILE_BYTES (128 * TSTRIDE)    // 34816 (128-row tile)
#define HTILE_BYTES (64 * TSTRIDE)    // 17408 (64-row tile)

// ---------------- kernel 1: fused prep = (q' & q_sq) + Gram G ---------------
__global__ __launch_bounds__(256) void prep_kernel(const float* __restrict__ q,
                                                   const float* __restrict__ W) {
    int t = threadIdx.x;
    if (blockIdx.x >= 1024) {
        int id = (blockIdx.x - 1024) * 256 + t;  // 0..16383
        int c1 = id >> 7, c2 = id & 127;
        float acc = 0.f;
#pragma unroll 8
        for (int d = 0; d < D_; ++d)
            acc = fmaf(__ldg(W + d * DC + c1), __ldg(W + d * DC + c2), acc);
        g_G[c1 * DC + c2] = __float2bfloat16(acc);
        return;
    }
    __shared__ float qs[8 * 256];
    size_t base = (size_t)blockIdx.x * 2048;
#pragma unroll
    for (int i = t; i < 2048; i += 256) qs[i] = q[base + i];
    __syncthreads();

    int lane = t & 31, w = t >> 5;
    float s = 0.f;
#pragma unroll
    for (int i = 0; i < 8; ++i) {
        float v = qs[w * 256 + lane + i * 32];
        s = fmaf(v, v, s);
    }
#pragma unroll
    for (int o = 16; o; o >>= 1) s += __shfl_xor_sync(0xffffffffu, s, o);
    if (lane == 0) g_qsq[blockIdx.x * 8 + w] = s;

    const float4* W4 = (const float4*)W;
    float ax = 0.f, ay = 0.f, az = 0.f, aw = 0.f;
#pragma unroll 4
    for (int d = 0; d < D_; ++d) {
        float qv = qs[w * 256 + d];
        float4 ww = W4[d * 32 + lane];
        ax = fmaf(qv, ww.x, ax);
        ay = fmaf(qv, ww.y, ay);
        az = fmaf(qv, ww.z, az);
        aw = fmaf(qv, ww.w, aw);
    }
    __nv_bfloat162 p01 = __floats2bfloat162_rn(ax, ay);
    __nv_bfloat162 p23 = __floats2bfloat162_rn(az, aw);
    uint2 wv = make_uint2(*reinterpret_cast<unsigned int*>(&p01),
                          *reinterpret_cast<unsigned int*>(&p23));
    ((uint2*)g_qp)[(blockIdx.x * 8 + w) * 32 + lane] = wv;
}

// ---------------- kernel 2: int4-code dequant -> bf16 -----------------------
__global__ void deq_kernel(const int* __restrict__ kq,
                           const float* __restrict__ sc,
                           const float* __restrict__ zp) {
    int i = blockIdx.x * 256 + threadIdx.x;
    int4 v = ((const int4*)kq)[i];
    int flat = i << 2;
    int c = flat & (DC - 1);
    int b = flat >> 20;
    float4 s = *(const float4*)(sc + b * DC + c);
    float4 z = *(const float4*)(zp + b * DC + c);
    float f0 = s.x * ((float)v.x - z.x);
    float f1 = s.y * ((float)v.y - z.y);
    float f2 = s.z * ((float)v.z - z.z);
    float f3 = s.w * ((float)v.w - z.w);
    __nv_bfloat162 p01 = __floats2bfloat162_rn(f0, f1);
    __nv_bfloat162 p23 = __floats2bfloat162_rn(f2, f3);
    uint2 wv = make_uint2(*reinterpret_cast<unsigned int*>(&p01),
                          *reinterpret_cast<unsigned int*>(&p23));
    ((uint2*)g_kc)[i] = wv;
}

// ---------------- mma.sync warp block: 32(M) x 64(N) x 128(K) ---------------
// Identical inner loop to the champion kernel; warp_m/warp_n ranges differ
// per caller. acc[mi][ni][4].
__device__ __forceinline__ void block_mma_warp(uint32_t smA, uint32_t smB,
                                               int lane, int warp_m, int warp_n,
                                               float acc[2][8][4]) {
#pragma unroll
    for (int kk = 0; kk < 8; ++kk) {
        uint32_t a[2][4];
#pragma unroll
        for (int mi = 0; mi < 2; ++mi) {
            int row = warp_m * 32 + mi * 16 + (lane & 15);
            uint32_t addr = smA + row * TSTRIDE + kk * 32 + ((lane >> 4) << 4);
            asm volatile("ldmatrix.sync.aligned.m8n8.x4.shared.b16 {%0,%1,%2,%3}, [%4];"
                         : "=r"(a[mi][0]), "=r"(a[mi][1]), "=r"(a[mi][2]), "=r"(a[mi][3])
                         : "r"(addr));
        }
        uint32_t bb[8][2];
#pragma unroll
        for (int nn = 0; nn < 4; ++nn) {
            int nrow = warp_n * 64 + nn * 16 + (lane & 7) + (((lane >> 4) & 1) << 3);
            uint32_t addr = smB + nrow * TSTRIDE + kk * 32 + (((lane >> 3) & 1) << 4);
            uint32_t r0, r1, r2, r3;
            asm volatile("ldmatrix.sync.aligned.m8n8.x4.shared.b16 {%0,%1,%2,%3}, [%4];"
                         : "=r"(r0), "=r"(r1), "=r"(r2), "=r"(r3)
                         : "r"(addr));
            bb[2 * nn][0] = r0; bb[2 * nn][1] = r1;
            bb[2 * nn + 1][0] = r2; bb[2 * nn + 1][1] = r3;
        }
#pragma unroll
        for (int mi = 0; mi < 2; ++mi)
#pragma unroll
            for (int ni = 0; ni < 8; ++ni)
                asm volatile(
                    "mma.sync.aligned.m16n8k16.row.col.f32.bf16.bf16.f32 "
                    "{%0,%1,%2,%3}, {%4,%5,%6,%7}, {%8,%9}, {%0,%1,%2,%3};"
                    : "+f"(acc[mi][ni][0]), "+f"(acc[mi][ni][1]),
                      "+f"(acc[mi][ni][2]), "+f"(acc[mi][ni][3])
                    : "r"(a[mi][0]), "r"(a[mi][1]), "r"(a[mi][2]), "r"(a[mi][3]),
                      "r"(bb[ni][0]), "r"(bb[ni][1]));
    }
}

// ---------------- kernel 3: k_sq via Gram quadratic form --------------------
__global__ __launch_bounds__(256) void ksq_kernel() {
    extern __shared__ char smem[];
    __nv_bfloat16* smA = (__nv_bfloat16*)smem;
    float* s_acc = (float*)(smem + 2 * TILE_BYTES);
    int t = threadIdx.x;
    int k0 = blockIdx.x * 128;

    const uint4* gA = (const uint4*)(g_kc + (size_t)k0 * DC);
    const uint4* gB = (const uint4*)g_G;
    uint4* sA4 = (uint4*)smem;
    uint4* sB4 = (uint4*)(smem + TILE_BYTES);
#pragma unroll
    for (int i = t; i < 2048; i += 256) {
        int r = i >> 4, ch = i & 15;
        sA4[r * 17 + ch] = gA[i];
        sB4[r * 17 + ch] = gB[i];
    }
    if (t < 128) s_acc[t] = 0.f;
    __syncthreads();

    int lane = t & 31, wid = t >> 5;
    int warp_m = wid & 3, warp_n = wid >> 2;
    float acc[2][8][4];
#pragma unroll
    for (int mi = 0; mi < 2; ++mi)
#pragma unroll
        for (int ni = 0; ni < 8; ++ni)
#pragma unroll
            for (int e = 0; e < 4; ++e) acc[mi][ni][e] = 0.f;

    block_mma_warp(smem_u32(smem), smem_u32(smem + TILE_BYTES),
                   lane, warp_m, warp_n, acc);

    int g = lane >> 2, tg = lane & 3;
#pragma unroll
    for (int mi = 0; mi < 2; ++mi)
#pragma unroll
        for (int h = 0; h < 2; ++h) {
            int row = warp_m * 32 + mi * 16 + h * 8 + g;
            float p = 0.f;
#pragma unroll
            for (int ni = 0; ni < 8; ++ni) {
                int col = warp_n * 64 + ni * 8 + 2 * tg;
                float kc0 = __bfloat162float(smA[row * 136 + col]);
                float kc1 = __bfloat162float(smA[row * 136 + col + 1]);
                p = fmaf(acc[mi][ni][2 * h + 0], kc0, p);
                p = fmaf(acc[mi][ni][2 * h + 1], kc1, p);
            }
            atomicAdd(&s_acc[row], p);
        }
    __syncthreads();
    if (t < 128) g_ksq[k0 + t] = s_acc[t];
}

// ---------------- kernel 4: distance kernel (64x128 CTAs, 4 CTAs/SM) -------
// SMEM: A[0,17408) B[17408,52224) s_ks[52224,52736) s_qsq[52736,52992)
#define DIST_SMEM 52992

__global__ __launch_bounds__(128, 4)
void dist_kernel(float* __restrict__ out) {
    extern __shared__ char smem[];
    float* s_ks  = (float*)(smem + 52224);   // 128 floats
    float* s_qsq = (float*)(smem + 52736);   // 64 floats
    const int t = threadIdx.x;
    const int lane = t & 31, wid = t >> 5;
    const int warp_m = wid & 1, warp_n = wid >> 1;   // 2(M) x 2(N) warps
    const int b = blockIdx.z, qt = blockIdx.y, kt = blockIdx.x;
    const int q0 = qt * 64, k0 = kt * 128;

    // loads: A = 64x128 q'-tile (1024 uint4), B = 128x128 kc-tile (2048 uint4)
    const uint4* gA = (const uint4*)(g_qp + (size_t)(b * LQ + q0) * DC);
    const uint4* gB = (const uint4*)(g_kc + (size_t)(b * LK + k0) * DC);
    uint4* sA4 = (uint4*)smem;
    uint4* sB4 = (uint4*)(smem + HTILE_BYTES);
#pragma unroll
    for (int i = t; i < 1024; i += 128) {
        int r = i >> 4, ch = i & 15;
        sA4[r * 17 + ch] = gA[i];
    }
#pragma unroll
    for (int i = t; i < 2048; i += 128) {
        int r = i >> 4, ch = i & 15;
        sB4[r * 17 + ch] = gB[i];
    }
    if (t < 128) s_ks[t] = __ldg(g_ksq + b * LK + k0 + t);
    if (t < 64)  s_qsq[t] = g_qsq[b * LQ + q0 + t];
    __syncthreads();

    float acc[2][8][4];
#pragma unroll
    for (int mi = 0; mi < 2; ++mi)
#pragma unroll
        for (int ni = 0; ni < 8; ++ni)
#pragma unroll
            for (int e = 0; e < 4; ++e) acc[mi][ni][e] = 0.f;

    block_mma_warp(smem_u32(smem), smem_u32(smem + HTILE_BYTES),
                   lane, warp_m, warp_n, acc);

    // ------------- epilogue -------------
    const int g = lane >> 2, tg = lane & 3;
    const float OME = 1.0f - EPS;
    const float E1 = 1.0f - OME;
    const float CDEN = fmaf(E1, E1, EPS);
    const float L2CDEN = __log2f(CDEN);
    const float THRC = 5.0e3f * CDEN;
    const float LN2 = 0.69314718056f, TWO_LN2 = 1.38629436112f;

    float qs_r[4], eq_r[4];
#pragma unroll
    for (int mi = 0; mi < 2; ++mi)
#pragma unroll
        for (int h = 0; h < 2; ++h) {
            int row = warp_m * 32 + mi * 16 + h * 8 + g;
            float qs = s_qsq[row];
            qs_r[mi * 2 + h] = qs;
            eq_r[mi * 2 + h] = 1.0f - fminf(qs, OME);
        }
    const bool rows_c = (qs_r[0] >= OME) & (qs_r[1] >= OME) &
                        (qs_r[2] >= OME) & (qs_r[3] >= OME);
    float* obase = out + (size_t)(b * LQ + q0) * LK + k0;

#pragma unroll
    for (int ni = 0; ni < 8; ++ni) {
        int col = warp_n * 64 + ni * 8 + 2 * tg;
        float ks0 = s_ks[col], ks1 = s_ks[col + 1];
        if (rows_c & (ks0 >= OME) & (ks1 >= OME)) {
            // den == CDEN for all outputs of this pair: 1 MUFU / element
#pragma unroll
            for (int mi = 0; mi < 2; ++mi)
#pragma unroll
                for (int h = 0; h < 2; ++h) {
                    float qs = qs_r[mi * 2 + h];
                    float d0 = fmaxf(fmaf(-2.0f, acc[mi][ni][2 * h + 0], qs + ks0), 0.0f);
                    float d1 = fmaxf(fmaf(-2.0f, acc[mi][ni][2 * h + 1], qs + ks1), 0.0f);
                    float r0 = (d0 > THRC)
                        ? fmaf(LN2, __log2f(d0) - L2CDEN, TWO_LN2)
                        : acoshf(1.0f + 2.0f * d0 / CDEN);
                    float r1 = (d1 > THRC)
                        ? fmaf(LN2, __log2f(d1) - L2CDEN, TWO_LN2)
                        : acoshf(1.0f + 2.0f * d1 / CDEN);
                    int row = warp_m * 32 + mi * 16 + h * 8 + g;
                    *(float2*)(obase + (size_t)row * LK + col) = make_float2(r0, r1);
                }
        } else {
            float ek0 = 1.0f - fminf(ks0, OME);
            float ek1 = 1.0f - fminf(ks1, OME);
#pragma unroll
            for (int mi = 0; mi < 2; ++mi)
#pragma unroll
                for (int h = 0; h < 2; ++h) {
                    float qs = qs_r[mi * 2 + h], eq = eq_r[mi * 2 + h];
                    float d0 = fmaxf(fmaf(-2.0f, acc[mi][ni][2 * h + 0], qs + ks0), 0.0f);
                    float d1 = fmaxf(fmaf(-2.0f, acc[mi][ni][2 * h + 1], qs + ks1), 0.0f);
                    float den0 = fmaf(eq, ek0, EPS);
                    float den1 = fmaf(eq, ek1, EPS);
                    float r0 = (d0 > 5.0e3f * den0)
                        ? fmaf(LN2, __log2f(d0) - __log2f(den0), TWO_LN2)
                        : acoshf(1.0f + 2.0f * d0 / den0);
                    float r1 = (d1 > 5.0e3f * den1)
                        ? fmaf(LN2, __log2f(d1) - __log2f(den1), TWO_LN2)
                        : acoshf(1.0f + 2.0f * d1 / den1);
                    int row = warp_m * 32 + mi * 16 + h * 8 + g;
                    *(float2*)(obase + (size_t)row * LK + col) = make_float2(r0, r1);
                }
        }
    }
}

// ---------------- launch ----------------------------------------------------
extern "C" void kernel_launch(void* const* d_in, const int* in_sizes, int n_in,
                              void* d_out, int out_size) {
    (void)in_sizes; (void)n_in; (void)out_size;
    const float* q   = (const float*)d_in[0];
    const int*   kq  = (const int*)d_in[1];
    const float* ksc = (const float*)d_in[2];
    const float* kzp = (const float*)d_in[3];
    const float* W   = (const float*)d_in[4];
    float* out = (float*)d_out;

    const int KSQ_SMEM = 2 * TILE_BYTES + 512;  // 70144
    cudaFuncSetAttribute(ksq_kernel, cudaFuncAttributeMaxDynamicSharedMemorySize, KSQ_SMEM);
    cudaFuncSetAttribute(dist_kernel, cudaFuncAttributeMaxDynamicSharedMemorySize, DIST_SMEM);

    prep_kernel<<<1088, 256>>>(q, W);                                 // launch 0
    deq_kernel<<<(B_ * LK * DC) / 4 / 256, 256>>>(kq, ksc, kzp);      // launch 1
    ksq_kernel<<<(B_ * LK) / 128, 256, KSQ_SMEM>>>();                 // launch 2
    dist_kernel<<<dim3(LK / 128, LQ / 64, B_), 128, DIST_SMEM>>>(out);  // launch 3
}